// round 16
// baseline (speedup 1.0000x reference)
#include <cuda_runtime.h>
#include <cuda_fp16.h>
#include <cstdint>

// Problem constants
#define B_    2
#define S_    2048
#define HID_  4096
#define NH_   32
#define NKV_  8
#define D_    128
#define NQKV  (NH_ * D_ + 2 * NKV_ * D_)   // 6144
#define NTASK (16 * NH_ * B_)              // 1024 flash tasks

// ---------------- scratch (__device__ globals; allocation-free) -------------
__device__ __half g_QKVh[(size_t)B_ * S_ * NQKV];      // fused QKV proj out (fp16)
__device__ __half g_Kh[(size_t)B_ * S_ * NKV_ * D_];   // roped K (fp16)
__device__ __half g_Vt[(size_t)B_ * NKV_ * D_ * S_];   // V transposed [b,kvh,d,s] fp16
__device__ __half g_Ah[(size_t)B_ * S_ * NH_ * D_];    // attn out (fp16)
__device__ __half g_Xh[(size_t)B_ * S_ * HID_];        // fp16 hidden states
__device__ __half g_Wqkvt[(size_t)NQKV * HID_];        // [6144, HID] transposed fp16
__device__ __half g_Wot[(size_t)HID_ * (NH_ * D_)];
__device__ int    g_ctr;                               // flash work-queue counter

__device__ __forceinline__ uint32_t smem_u32(const void* p) {
    uint32_t a;
    asm("{ .reg .u64 t; cvta.to.shared.u64 t, %1; cvt.u32.u64 %0, t; }" : "=r"(a) : "l"(p));
    return a;
}
__device__ __forceinline__ void cp16(uint32_t saddr, const void* g) {
    asm volatile("cp.async.cg.shared.global [%0], [%1], 16;" :: "r"(saddr), "l"(g));
}
#define CP_COMMIT() asm volatile("cp.async.commit_group;" ::: "memory")
#define CP_WAIT(n)  asm volatile("cp.async.wait_group %0;" :: "n"(n) : "memory")

__device__ __forceinline__ void ldm_x4(uint32_t* r, uint32_t addr) {
    asm volatile("ldmatrix.sync.aligned.m8n8.x4.shared.b16 {%0,%1,%2,%3}, [%4];"
        : "=r"(r[0]), "=r"(r[1]), "=r"(r[2]), "=r"(r[3]) : "r"(addr));
}
__device__ __forceinline__ float ex2f(float x) {
    float y;
    asm("ex2.approx.f32 %0, %1;" : "=f"(y) : "f"(x));
    return y;
}
__device__ __forceinline__ uint32_t packh2(float a, float b) {
    __half2 h = __floats2half2_rn(a, b);
    return *(uint32_t*)&h;
}

// Epilogue store helpers (fp32 or fp16 C)
__device__ __forceinline__ void store2(float* p, float a, float b) {
    *(float2*)p = make_float2(a, b);
}
__device__ __forceinline__ void store2(__half* p, float a, float b) {
    *(__half2*)p = __floats2half2_rn(a, b);
}

// ---------------- pre-pass kernels ------------------------------------------
// X -> fp16; also zeroes the flash work-queue counter (block 0, thread 0).
__global__ void cvt_half_kernel(const float* __restrict__ in, __half* __restrict__ out, int n4) {
    if (blockIdx.x == 0 && threadIdx.x == 0) g_ctr = 0;
    int i = blockIdx.x * blockDim.x + threadIdx.x;
    if (i < n4) {
        float4 v = ((const float4*)in)[i];
        ((__half2*)out)[i * 2]     = __floats2half2_rn(v.x, v.y);
        ((__half2*)out)[i * 2 + 1] = __floats2half2_rn(v.z, v.w);
    }
}

// All four weight transposes in ONE launch. Tile ranges (32x32 tiles, blk (32,8)):
//   [0,16384)        Wq -> Wqkvt            (N=4096, K=4096)
//   [16384,20480)    Wk -> Wqkvt+NQ*HID     (N=1024, K=4096)
//   [20480,24576)    Wv -> Wqkvt+(NQ+NKVD)*HID
//   [24576,40960)    Wo -> Wot              (N=4096, K=4096)
__global__ void transpose_all_kernel(const float* __restrict__ Wq, const float* __restrict__ Wk,
                                     const float* __restrict__ Wv, const float* __restrict__ Wo,
                                     __half* __restrict__ Wqkvt, __half* __restrict__ Wot) {
    __shared__ float t[32][33];
    const int bid = blockIdx.x;
    const float* W;
    __half* Wt;
    int N, local;
    if (bid < 16384)       { W = Wq; Wt = Wqkvt;                                   N = 4096; local = bid; }
    else if (bid < 20480)  { W = Wk; Wt = Wqkvt + (size_t)(NH_ * D_) * HID_;       N = 1024; local = bid - 16384; }
    else if (bid < 24576)  { W = Wv; Wt = Wqkvt + (size_t)((NH_ + NKV_) * D_) * HID_; N = 1024; local = bid - 20480; }
    else                   { W = Wo; Wt = Wot;                                     N = 4096; local = bid - 24576; }
    const int K = 4096;                         // all weights have K=4096 rows here
    const int ntiles = N >> 5;
    const int n0 = (local % ntiles) * 32;
    const int k0 = (local / ntiles) * 32;
    const int tx = threadIdx.x, ty = threadIdx.y;
#pragma unroll
    for (int j = 0; j < 32; j += 8)
        t[ty + j][tx] = W[(size_t)(k0 + ty + j) * N + n0 + tx];
    __syncthreads();
#pragma unroll
    for (int j = 0; j < 32; j += 8)
        Wt[(size_t)(n0 + ty + j) * K + k0 + tx] = __float2half_rn(t[tx][ty + j]);
}

// K RoPE (blocks [0,4096)) + V transpose (blocks [4096,8192)) in one launch.
__global__ __launch_bounds__(256) void ropekh_vt_kernel(const __half* __restrict__ QKV,
                                                        __half* __restrict__ Kh,
                                                        __half* __restrict__ Vt,
                                                        const float* __restrict__ cosc,
                                                        const float* __restrict__ sinc) {
    __shared__ __half t[32][40];
    if (blockIdx.x < 4096) {
        // ---- K RoPE -> fp16 ----
        const int idx = blockIdx.x * 256 + threadIdx.x;
        const int r = idx >> 4;
        const int c4 = (idx & 15) << 2;
        const int bs = r / NKV_, kvh = r % NKV_;
        const int s = bs % S_;
        const __half* row = QKV + (size_t)bs * NQKV + NH_ * D_ + kvh * D_;
        __half2 a0 = *(const __half2*)(row + c4);
        __half2 a1 = *(const __half2*)(row + c4 + 2);
        __half2 b0 = *(const __half2*)(row + c4 + 64);
        __half2 b1 = *(const __half2*)(row + c4 + 66);
        float x1[4] = {__low2float(a0), __high2float(a0), __low2float(a1), __high2float(a1)};
        float x2[4] = {__low2float(b0), __high2float(b0), __low2float(b1), __high2float(b1)};
        float4 c0 = *(const float4*)(cosc + s * D_ + c4);
        float4 s0 = *(const float4*)(sinc + s * D_ + c4);
        float4 c1 = *(const float4*)(cosc + s * D_ + c4 + 64);
        float4 s1 = *(const float4*)(sinc + s * D_ + c4 + 64);
        float cc0[4] = {c0.x, c0.y, c0.z, c0.w}, ss0[4] = {s0.x, s0.y, s0.z, s0.w};
        float cc1[4] = {c1.x, c1.y, c1.z, c1.w}, ss1[4] = {s1.x, s1.y, s1.z, s1.w};
        float o1[4], o2[4];
#pragma unroll
        for (int j = 0; j < 4; j++) {
            o1[j] = x1[j] * cc0[j] - x2[j] * ss0[j];
            o2[j] = x2[j] * cc1[j] + x1[j] * ss1[j];
        }
        __half* ph = Kh + (size_t)r * D_;
        *(__half2*)(ph + c4)     = __floats2half2_rn(o1[0], o1[1]);
        *(__half2*)(ph + c4 + 2) = __floats2half2_rn(o1[2], o1[3]);
        *(__half2*)(ph + c4 + 64)     = __floats2half2_rn(o2[0], o2[1]);
        *(__half2*)(ph + c4 + 64 + 2) = __floats2half2_rn(o2[2], o2[3]);
    } else {
        // ---- V transpose: [b,s,kvh,d] -> [b,kvh,d,s] ----
        const int local = blockIdx.x - 4096;           // was grid (64, 4, 16)
        const int s0 = (local & 63) * 32;
        const int d0 = ((local >> 6) & 3) * 32;
        const int bk = local >> 8;
        const int tx = threadIdx.x & 31, ty = threadIdx.x >> 5;
        const int b = bk / NKV_, kvh = bk % NKV_;
#pragma unroll
        for (int j = 0; j < 32; j += 8)
            t[ty + j][tx] = QKV[(size_t)(b * S_ + s0 + ty + j) * NQKV +
                                (NH_ + NKV_) * D_ + kvh * D_ + d0 + tx];
        __syncthreads();
#pragma unroll
        for (int j = 0; j < 32; j += 8)
            Vt[((size_t)(bk * D_ + d0 + ty + j)) * S_ + s0 + tx] = t[tx][ty + j];
    }
}

// ---------------- mma helper --------------------------------------------------
__device__ __forceinline__ void mma_f16(float* c, const uint32_t* a, const uint32_t* b) {
    asm volatile(
        "mma.sync.aligned.m16n8k16.row.col.f32.f16.f16.f32 "
        "{%0,%1,%2,%3}, {%4,%5,%6,%7}, {%8,%9}, {%0,%1,%2,%3};"
        : "+f"(c[0]), "+f"(c[1]), "+f"(c[2]), "+f"(c[3])
        : "r"(a[0]), "r"(a[1]), "r"(a[2]), "r"(a[3]), "r"(b[0]), "r"(b[1]));
}

// ---------------- fp16 mma.sync GEMM (3-stage cp.async) ----------------------
#define BM 128
#define BN 128
#define BKH 64
#define TSTRH 72
#define TILE_HALFS (128 * TSTRH)
#define STAGE_HALFS (2 * TILE_HALFS)
#define NSTG 3
#define GSM_BYTES (NSTG * STAGE_HALFS * 2)   // 110592

__device__ __forceinline__ void g2s_cp_h(const __half* __restrict__ G, uint32_t sbase,
                                         int row0, int K, int k0, int tid) {
#pragma unroll
    for (int i = 0; i < 4; i++) {
        int lin = tid + i * 256;
        int r = lin >> 3, c = lin & 7;
        cp16(sbase + (uint32_t)(r * TSTRH + c * 8) * 2u,
             G + (size_t)(row0 + r) * K + k0 + c * 8);
    }
}

template <typename OutT>
__global__ __launch_bounds__(256) void tc_gemm(const __half* __restrict__ A,
                                               const __half* __restrict__ Bt,
                                               OutT* __restrict__ C,
                                               int M, int N, int K) {
    extern __shared__ __half smh[];
    const uint32_t smb = smem_u32(smh);

    const int tid = threadIdx.x;
    const int lane = tid & 31, wid = tid >> 5;
    const int warpM = wid & 3;
    const int warpN = wid >> 2;
    const int ty8 = lane >> 2;
    const int tx4 = lane & 3;
    const int lane7 = lane & 7, seg = lane >> 3;
    const int bm = blockIdx.y * BM, bn = blockIdx.x * BN;

    uint32_t a_offb[2], b_offb[4];
#pragma unroll
    for (int mi = 0; mi < 2; mi++)
        a_offb[mi] = (uint32_t)(((warpM * 32 + mi * 16 + (seg & 1) * 8 + lane7) * TSTRH
                                 + (seg >> 1) * 8) * 2);
#pragma unroll
    for (int p = 0; p < 4; p++)
        b_offb[p] = (uint32_t)(((warpN * 64 + p * 16 + (seg >> 1) * 8 + lane7) * TSTRH
                                 + (seg & 1) * 8) * 2);

    float acc[2][8][4];
#pragma unroll
    for (int mi = 0; mi < 2; mi++)
#pragma unroll
        for (int ni = 0; ni < 8; ni++)
#pragma unroll
            for (int r = 0; r < 4; r++) acc[mi][ni][r] = 0.f;

    const int NK = K / BKH;
    g2s_cp_h(A, smb, bm, K, 0, tid);
    g2s_cp_h(Bt, smb + TILE_HALFS * 2, bn, K, 0, tid);
    CP_COMMIT();
    if (NK > 1) {
        g2s_cp_h(A, smb + STAGE_HALFS * 2, bm, K, BKH, tid);
        g2s_cp_h(Bt, smb + (STAGE_HALFS + TILE_HALFS) * 2, bn, K, BKH, tid);
        CP_COMMIT();
    }

    int buf = 0;
    for (int kt = 0; kt < NK; kt++) {
        if (kt + 2 < NK) {
            int pre = buf + 2; if (pre >= NSTG) pre -= NSTG;
            g2s_cp_h(A, smb + (uint32_t)(pre * STAGE_HALFS) * 2, bm, K, (kt + 2) * BKH, tid);
            g2s_cp_h(Bt, smb + (uint32_t)(pre * STAGE_HALFS + TILE_HALFS) * 2, bn, K, (kt + 2) * BKH, tid);
            CP_COMMIT();
            CP_WAIT(2);
        } else if (kt + 1 < NK) {
            CP_WAIT(1);
        } else {
            CP_WAIT(0);
        }
        __syncthreads();

        const uint32_t asu = smb + (uint32_t)(buf * STAGE_HALFS) * 2;
        const uint32_t bsu = asu + TILE_HALFS * 2;
#pragma unroll
        for (int ks = 0; ks < 4; ks++) {
            const uint32_t kb = (uint32_t)(ks * 16 * 2);
            uint32_t af[2][4];
            ldm_x4(af[0], asu + a_offb[0] + kb);
            ldm_x4(af[1], asu + a_offb[1] + kb);
            uint32_t bf[8][2];
#pragma unroll
            for (int p = 0; p < 4; p++) {
                uint32_t t[4];
                ldm_x4(t, bsu + b_offb[p] + kb);
                bf[2 * p][0] = t[0];     bf[2 * p][1] = t[1];
                bf[2 * p + 1][0] = t[2]; bf[2 * p + 1][1] = t[3];
            }
#pragma unroll
            for (int mi = 0; mi < 2; mi++)
#pragma unroll
                for (int ni = 0; ni < 8; ni++)
                    mma_f16(acc[mi][ni], af[mi], bf[ni]);
        }
        __syncthreads();
        if (++buf == NSTG) buf = 0;
    }

#pragma unroll
    for (int mi = 0; mi < 2; mi++) {
        const int r0 = bm + warpM * 32 + mi * 16 + ty8;
#pragma unroll
        for (int ni = 0; ni < 8; ni++) {
            const int cc = bn + warpN * 64 + ni * 8 + 2 * tx4;
            store2(C + (size_t)r0 * N + cc, acc[mi][ni][0], acc[mi][ni][1]);
            store2(C + (size_t)(r0 + 8) * N + cc, acc[mi][ni][2], acc[mi][ni][3]);
        }
    }
}

// ---------------- persistent flash attention ---------------------------------
// P in registers; atomic work queue; split K/V cp.async groups (QK waits only K).
#define QS_STR  136
#define KH_STR  136
#define VT_STR  72
#define KH_BYTES (64 * KH_STR * 2)           // 17408
#define VT_BYTES (128 * VT_STR * 2)          // 18432
#define STG_BYTES (KH_BYTES + VT_BYTES)      // 35840
#define FL_SMEM_BYTES (2 * STG_BYTES)        // 71680
#define FL_GRID 296

__device__ __forceinline__ void flash_stage_k(const __half* __restrict__ Khg,
                                              uint32_t sb, int b, int kvh,
                                              int kbase, int tid) {
#pragma unroll
    for (int i = 0; i < 4; i++) {
        int lin = tid + i * 256;
        int r = lin >> 4, c = lin & 15;
        cp16(sb + (uint32_t)(r * KH_STR + c * 8) * 2u,
             Khg + ((size_t)((b * S_ + kbase + r) * NKV_ + kvh)) * D_ + c * 8);
    }
}
__device__ __forceinline__ void flash_stage_v(const __half* __restrict__ Vt,
                                              uint32_t sb, int b, int kvh,
                                              int kbase, int tid) {
#pragma unroll
    for (int i = 0; i < 4; i++) {
        int lin = tid + i * 256;
        int r = lin >> 3, c = lin & 7;
        cp16(sb + KH_BYTES + (uint32_t)(r * VT_STR + c * 8) * 2u,
             Vt + ((size_t)((b * NKV_ + kvh) * D_ + r)) * S_ + kbase + c * 8);
    }
}

__global__ __launch_bounds__(256) void flash_mma_kernel(
    const __half* __restrict__ QKV, const __half* __restrict__ Khg,
    const __half* __restrict__ Vt, const float* __restrict__ cosc,
    const float* __restrict__ sinc, __half* __restrict__ Og) {
    extern __shared__ char smc[];
    __shared__ int s_task;
    const uint32_t smb = smem_u32(smc);
    __half* Qstage = (__half*)smc;

    const int tid = threadIdx.x;
    const int lane = tid & 31, wid = tid >> 5;
    const int ty8 = lane >> 2;
    const int tx4 = lane & 3;
    const int lane7 = lane & 7, seg = lane >> 3;
    const int wrow = wid * 16;
    const float scale = 0.08838834764831845f * 1.44269504088896340f;

    const uint32_t qa_offb = (uint32_t)(((wrow + (seg & 1) * 8 + lane7) * QS_STR
                                         + (seg >> 1) * 8) * 2);
    uint32_t kb_offb[4];
#pragma unroll
    for (int p = 0; p < 4; p++)
        kb_offb[p] = (uint32_t)(((p * 16 + (seg >> 1) * 8 + lane7) * KH_STR
                                  + (seg & 1) * 8) * 2);
    uint32_t vb_offb[8];
#pragma unroll
    for (int p = 0; p < 8; p++)
        vb_offb[p] = (uint32_t)(((p * 16 + (seg >> 1) * 8 + lane7) * VT_STR
                                  + (seg & 1) * 8) * 2);

    for (;;) {
        if (tid == 0) s_task = atomicAdd(&g_ctr, 1);
        __syncthreads();
        const int t = s_task;
        __syncthreads();
        if (t >= NTASK) break;
        const int qt = 15 - (t >> 6);          // LPT: heaviest first
        const int h  = t & 31;
        const int b  = (t >> 5) & 1;
        const int kvh = h >> 2;
        const int qbase = qt * 128;

        // ---- stage Q: fused RoPE + scale*log2e + fp16 ----
#pragma unroll
        for (int i = 0; i < 8; i++) {
            int lin = i * 256 + tid;
            int r = lin >> 4;
            int c4 = (lin & 15) << 2;
            const int sg = qbase + r;
            const __half* qrow = QKV + (size_t)(b * S_ + sg) * NQKV + h * D_;
            __half2 a0 = *(const __half2*)(qrow + c4);
            __half2 a1 = *(const __half2*)(qrow + c4 + 2);
            __half2 b0h = *(const __half2*)(qrow + c4 + 64);
            __half2 b1h = *(const __half2*)(qrow + c4 + 66);
            float x1[4] = {__low2float(a0), __high2float(a0), __low2float(a1), __high2float(a1)};
            float x2[4] = {__low2float(b0h), __high2float(b0h), __low2float(b1h), __high2float(b1h)};
            float4 c0 = *(const float4*)(cosc + sg * D_ + c4);
            float4 s0 = *(const float4*)(sinc + sg * D_ + c4);
            float4 c1 = *(const float4*)(cosc + sg * D_ + c4 + 64);
            float4 s1 = *(const float4*)(sinc + sg * D_ + c4 + 64);
            float cc0[4] = {c0.x, c0.y, c0.z, c0.w}, ss0[4] = {s0.x, s0.y, s0.z, s0.w};
            float cc1[4] = {c1.x, c1.y, c1.z, c1.w}, ss1[4] = {s1.x, s1.y, s1.z, s1.w};
#pragma unroll
            for (int j = 0; j < 4; j++) {
                float o1 = x1[j] * cc0[j] - x2[j] * ss0[j];
                float o2 = x2[j] * cc1[j] + x1[j] * ss1[j];
                Qstage[r * QS_STR + c4 + j]      = __float2half_rn(o1 * scale);
                Qstage[r * QS_STR + c4 + 64 + j] = __float2half_rn(o2 * scale);
            }
        }
        __syncthreads();

        uint32_t qf[8][4];
#pragma unroll
        for (int ks = 0; ks < 8; ks++)
            ldm_x4(qf[ks], smb + qa_offb + (uint32_t)(ks * 32));
        __syncthreads();

        float m_i[2] = {-1e30f, -1e30f};
        float l_i[2] = {0.f, 0.f};
        float oacc[16][4];
#pragma unroll
        for (int ni = 0; ni < 16; ni++)
#pragma unroll
            for (int r = 0; r < 4; r++) oacc[ni][r] = 0.f;

        const int NKT = 2 * qt + 2;
        // Prologue: K and V of tile 0 as separate groups
        flash_stage_k(Khg, smb, b, kvh, 0, tid);
        CP_COMMIT();
        flash_stage_v(Vt, smb, b, kvh, 0, tid);
        CP_COMMIT();

        for (int kt = 0; kt < NKT; kt++) {
            const int kbase = kt * 64;
            const int buf = kt & 1;
            const bool more = (kt + 1 < NKT);
            if (more) {
                flash_stage_k(Khg, smb + (buf ^ 1) * STG_BYTES, b, kvh, kbase + 64, tid);
                CP_COMMIT();
                flash_stage_v(Vt, smb + (buf ^ 1) * STG_BYTES, b, kvh, kbase + 64, tid);
                CP_COMMIT();
                CP_WAIT(3);            // K(kt) done; V(kt),K(kt+1),V(kt+1) may remain
            } else {
                CP_WAIT(1);            // K(kt) done; V(kt) may remain
            }
            __syncthreads();

            const bool active = (qbase + wrow + 15 >= kbase);
            const uint32_t khu = smb + buf * STG_BYTES;
            const uint32_t vsu = khu + KH_BYTES;
            float sc[8][4];

            if (active) {
                // ---- QK^T (K only) ----
#pragma unroll
                for (int ni = 0; ni < 8; ni++)
#pragma unroll
                    for (int r = 0; r < 4; r++) sc[ni][r] = 0.f;
#pragma unroll
                for (int ks = 0; ks < 8; ks++) {
                    const uint32_t kb = (uint32_t)(ks * 32);
#pragma unroll
                    for (int p = 0; p < 4; p++) {
                        uint32_t kf[4];
                        ldm_x4(kf, khu + kb_offb[p] + kb);
                        mma_f16(sc[2 * p], qf[ks], kf);
                        mma_f16(sc[2 * p + 1], qf[ks], kf + 2);
                    }
                }

                // ---- causal mask ----
                if (kbase + 63 > qbase) {
#pragma unroll
                    for (int ni = 0; ni < 8; ni++) {
#pragma unroll
                        for (int r = 0; r < 4; r++) {
                            int row = qbase + wrow + ty8 + ((r >= 2) ? 8 : 0);
                            int col = kbase + ni * 8 + 2 * tx4 + (r & 1);
                            if (col > row) sc[ni][r] = -1e30f;
                        }
                    }
                }

                // ---- online softmax (base-2) ----
#pragma unroll
                for (int rh = 0; rh < 2; rh++) {
                    const int i0 = rh * 2, i1 = rh * 2 + 1;
                    float mloc = -1e30f;
#pragma unroll
                    for (int ni = 0; ni < 8; ni++)
                        mloc = fmaxf(mloc, fmaxf(sc[ni][i0], sc[ni][i1]));
                    mloc = fmaxf(mloc, __shfl_xor_sync(0xffffffffu, mloc, 1));
                    mloc = fmaxf(mloc, __shfl_xor_sync(0xffffffffu, mloc, 2));
                    const float mnew = fmaxf(m_i[rh], mloc);
                    const bool changed = mnew > m_i[rh];
                    const float fac = ex2f(m_i[rh] - mnew);
                    m_i[rh] = mnew;
                    float rsum = 0.f;
#pragma unroll
                    for (int ni = 0; ni < 8; ni++) {
                        float p0 = ex2f(sc[ni][i0] - mnew);
                        float p1 = ex2f(sc[ni][i1] - mnew);
                        sc[ni][i0] = p0; sc[ni][i1] = p1;
                        rsum += p0 + p1;
                    }
                    rsum += __shfl_xor_sync(0xffffffffu, rsum, 1);
                    rsum += __shfl_xor_sync(0xffffffffu, rsum, 2);
                    l_i[rh] = l_i[rh] * fac + rsum;
                    if (__any_sync(0xffffffffu, changed)) {
#pragma unroll
                        for (int ni = 0; ni < 16; ni++) {
                            oacc[ni][i0] *= fac;
                            oacc[ni][i1] *= fac;
                        }
                    }
                }
            }

            // ---- V wait (deferred past QK+softmax) ----
            if (more) { CP_WAIT(2); } else { CP_WAIT(0); }
            __syncthreads();

            if (active) {
                // ---- PV: P never leaves registers ----
#pragma unroll
                for (int ks = 0; ks < 4; ks++) {
                    uint32_t af[4];
                    af[0] = packh2(sc[2 * ks][0], sc[2 * ks][1]);
                    af[1] = packh2(sc[2 * ks][2], sc[2 * ks][3]);
                    af[2] = packh2(sc[2 * ks + 1][0], sc[2 * ks + 1][1]);
                    af[3] = packh2(sc[2 * ks + 1][2], sc[2 * ks + 1][3]);
                    const uint32_t kb = (uint32_t)(ks * 32);
#pragma unroll
                    for (int p = 0; p < 8; p++) {
                        uint32_t vf[4];
                        ldm_x4(vf, vsu + vb_offb[p] + kb);
                        mma_f16(oacc[2 * p], af, vf);
                        mma_f16(oacc[2 * p + 1], af, vf + 2);
                    }
                }
            }
            __syncthreads();
        }

        // ---- epilogue ----
        const float inv0 = 1.0f / l_i[0];
        const float inv1 = 1.0f / l_i[1];
        const int r0 = qbase + wrow + ty8;
#pragma unroll
        for (int ni = 0; ni < 16; ni++) {
            const int cc = ni * 8 + 2 * tx4;
            __half* p0 = Og + ((size_t)((b * S_ + r0) * NH_ + h)) * D_ + cc;
            __half* p1 = Og + ((size_t)((b * S_ + r0 + 8) * NH_ + h)) * D_ + cc;
            *(__half2*)p0 = __floats2half2_rn(oacc[ni][0] * inv0, oacc[ni][1] * inv0);
            *(__half2*)p1 = __floats2half2_rn(oacc[ni][2] * inv1, oacc[ni][3] * inv1);
        }
    }
}

// ---------------- launch ----------------------------------------------------
extern "C" void kernel_launch(void* const* d_in, const int* in_sizes, int n_in,
                              void* d_out, int out_size) {
    const float* X    = (const float*)d_in[0];
    const float* Wq   = (const float*)d_in[1];
    const float* Wk   = (const float*)d_in[2];
    const float* Wv   = (const float*)d_in[3];
    const float* Wo   = (const float*)d_in[4];
    const float* cosc = (const float*)d_in[5];
    const float* sinc = (const float*)d_in[6];
    float* out = (float*)d_out;

    __half *QKVh, *Khp, *Vtp, *Ah, *Xh, *Wqkvt, *Wot;
    cudaGetSymbolAddress((void**)&QKVh, g_QKVh);
    cudaGetSymbolAddress((void**)&Khp, g_Kh);
    cudaGetSymbolAddress((void**)&Vtp, g_Vt);
    cudaGetSymbolAddress((void**)&Ah, g_Ah);
    cudaGetSymbolAddress((void**)&Xh, g_Xh);
    cudaGetSymbolAddress((void**)&Wqkvt, g_Wqkvt);
    cudaGetSymbolAddress((void**)&Wot, g_Wot);

    const int M = B_ * S_;          // 4096
    const int NQ = NH_ * D_;        // 4096

    // Pre-pass (2 launches): X->fp16 (+ctr zero); all weight transposes
    {
        int n4 = M * HID_ / 4;
        cvt_half_kernel<<<(n4 + 255) / 256, 256>>>(X, Xh, n4);
        dim3 blk(32, 8);
        transpose_all_kernel<<<40960, blk>>>(Wq, Wk, Wv, Wo, Wqkvt, Wot);
    }

    cudaFuncSetAttribute(tc_gemm<__half>, cudaFuncAttributeMaxDynamicSharedMemorySize, GSM_BYTES);
    cudaFuncSetAttribute(tc_gemm<float>, cudaFuncAttributeMaxDynamicSharedMemorySize, GSM_BYTES);

    // Fused QKV projection (fp16 output)
    tc_gemm<__half><<<dim3(NQKV / BN, M / BM), 256, GSM_BYTES>>>(Xh, Wqkvt, QKVh, M, NQKV, HID_);

    // K RoPE + V transpose (one launch)
    ropekh_vt_kernel<<<8192, 256>>>(QKVh, Khp, Vtp, cosc, sinc);

    // Persistent flash attention
    cudaFuncSetAttribute(flash_mma_kernel, cudaFuncAttributeMaxDynamicSharedMemorySize, FL_SMEM_BYTES);
    flash_mma_kernel<<<FL_GRID, 256, FL_SMEM_BYTES>>>(QKVh, Khp, Vtp, cosc, sinc, Ah);

    // Output projection (fp32 output)
    tc_gemm<float><<<dim3(HID_ / BN, M / BM), 256, GSM_BYTES>>>(Ah, Wot, out, M, HID_, NQ);
}